// round 11
// baseline (speedup 1.0000x reference)
#include <cuda_runtime.h>
#include <cuda_bf16.h>
#include <math.h>

#define IMG_H 768
#define IMG_W 768
#define IMG_B 16
#define NPIXD 9437184.0
#define TILE 32
#define RAW_W 53            /* cols gx0-12 .. gx0+40 */
#define RAW_H 50            /* rows gy0-9  .. gy0+40 */
#define H3STR 33
#define H1ROWS 38
#define BINS 4096
#define NACC 15
#define GRID_X 24
#define GRID_Y 24
#define NBLOCKS (GRID_X*GRID_Y*IMG_B)
#define SMEM_FLOATS 15408   /* 61632 bytes */

/* smem float offsets:
   [0,5300)      s_xy  : 2650 float2 (xi,yp) raw tile
   [5300,7950)   s_u   : 2650 float  (U = yp - .3 xi - .7 xm)
   [7950,11250)  h3xy  : 1650 float2, idx row*33+col
   [11250,12900) h3u   : 1650 float
   [12900,15408) h1xy  : 1254 float2 */

__device__ double       g_acc[NACC];
__device__ unsigned int g_hist[2*BINS];   /* [0,BINS)=yp(body)  [BINS,2BINS)=x_i(body) */
__device__ unsigned int g_done;

#define G3_INIT {0.00147946f,0.00380425f,0.00875347f,0.01802342f,0.03320773f,\
                 0.05475029f,0.08077532f,0.10663899f,0.12597909f,0.13317599f,\
                 0.12597909f,0.10663899f,0.08077532f,0.05475029f,0.03320773f,\
                 0.01802342f,0.00875347f,0.00380425f,0.00147946f}
#define G1_INIT {0.00443305f,0.05400558f,0.24203624f,0.39905030f,0.24203624f,\
                 0.05400558f,0.00443305f}

__global__ void __launch_bounds__(256, 3) k_main(
    const float* __restrict__ ypred, const float* __restrict__ npred,
    const float* __restrict__ xi,    const float* __restrict__ xmid,
    const float* __restrict__ wmap,  const float* __restrict__ nsyn,
    float* __restrict__ out)
{
    const float G3W[19] = G3_INIT;
    const float G1W[7]  = G1_INIT;

    extern __shared__ float sm[];
    float2* s_xy = (float2*)sm;              /* 2650 float2 */
    float*  s_u  = sm + 5300;
    float2* h3xy = (float2*)(sm + 7950);     /* 1650 float2 */
    float*  h3u  = sm + 11250;
    float2* h1xy = (float2*)(sm + 12900);    /* 1254 float2 */

    __shared__ double s_red[NACC];
    __shared__ unsigned int s_islast;

    const int tid = threadIdx.x;
    if (tid < NACC) s_red[tid] = 0.0;

    const int gx0 = blockIdx.x * TILE;
    const int gy0 = blockIdx.y * TILE;
    const size_t base = (size_t)blockIdx.z * (IMG_H*IMG_W);
    const bool xsafe = (blockIdx.x > 0) && (blockIdx.x < GRID_X-1);

    /* ---- phase 1: load halo tiles; interleave (xi,yp); U = yp-.3xi-.7xm ---- */
    for (int idx = tid; idx < RAW_H*14; idx += 256) {
        int row = idx / 14, q = idx - row*14;
        int sc = q*4;
        int gy = gy0 + row - 9;
        float ai[4] = {0.f,0.f,0.f,0.f};
        float ap[4] = {0.f,0.f,0.f,0.f};
        float am[4] = {0.f,0.f,0.f,0.f};
        if ((unsigned)gy < IMG_H) {
            int gxs = gx0 - 12 + sc;
            size_t g = base + (size_t)gy*IMG_W + gxs;
            if (xsafe) {
                float4 vi = *(const float4*)(xi+g);
                float4 vp = *(const float4*)(ypred+g);
                float4 vm = *(const float4*)(xmid+g);
                ai[0]=vi.x; ai[1]=vi.y; ai[2]=vi.z; ai[3]=vi.w;
                ap[0]=vp.x; ap[1]=vp.y; ap[2]=vp.z; ap[3]=vp.w;
                am[0]=vm.x; am[1]=vm.y; am[2]=vm.z; am[3]=vm.w;
            } else {
#pragma unroll
                for (int e = 0; e < 4; e++) {
                    if ((unsigned)(gxs+e) < IMG_W) {
                        ai[e] = xi[g+e]; ap[e] = ypred[g+e]; am[e] = xmid[g+e];
                    }
                }
            }
        }
        int o = row*RAW_W + sc;
#pragma unroll
        for (int e = 0; e < 4; e++) {
            if (sc+e < RAW_W) {
                s_xy[o+e] = make_float2(ai[e], ap[e]);
                s_u[o+e]  = ap[e] - 0.3f*ai[e] - 0.7f*am[e];
            }
        }
    }
    __syncthreads();

    /* ---- phase 2: horizontal convs (dense mapping), float2 for (xi,yp) ---- */
    {
        const int row = tid >> 2, seg = tid & 3;
        if (row < RAW_H) {
            const int bi = row*RAW_W + seg*8 + 3;
            const int bo = row*H3STR + seg*8;
            {
                float2 w2[26];
#pragma unroll
                for (int j = 0; j < 26; j++) w2[j] = s_xy[bi+j];
#pragma unroll
                for (int i = 0; i < 8; i++) {
                    float ax = 0.f, ay = 0.f;
#pragma unroll
                    for (int k = 0; k < 19; k++) {
                        float g = G3W[k];
                        ax = fmaf(w2[i+k].x, g, ax);
                        ay = fmaf(w2[i+k].y, g, ay);
                    }
                    h3xy[bo+i] = make_float2(ax, ay);
                }
            }
            {
                float wu[26];
#pragma unroll
                for (int j = 0; j < 26; j++) wu[j] = s_u[bi+j];
#pragma unroll
                for (int i = 0; i < 8; i++) {
                    float a = 0.f;
#pragma unroll
                    for (int k = 0; k < 19; k++) a = fmaf(wu[i+k], G3W[k], a);
                    h3u[bo+i] = a;
                }
            }
        }
        if (row < H1ROWS) {
            const int bi = (row+6)*RAW_W + seg*8 + 9;
            const int bo = row*H3STR + seg*8;
            float2 u2[14];
#pragma unroll
            for (int j = 0; j < 14; j++) u2[j] = s_xy[bi+j];
#pragma unroll
            for (int i = 0; i < 8; i++) {
                float ax = 0.f, ay = 0.f;
#pragma unroll
                for (int k = 0; k < 7; k++) {
                    float g = G1W[k];
                    ax = fmaf(u2[i+k].x, g, ax);
                    ay = fmaf(u2[i+k].y, g, ay);
                }
                h1xy[bo+i] = make_float2(ax, ay);
            }
        }
    }
    __syncthreads();

    /* ---- phase 3: vertical convs -> A = G3*U, B = (G1-G3)*xi, C = (G1-G3)*yp ---- */
    const int c  = tid & 31;
    const int r0 = (tid >> 5) << 2;

    float A4[4], B4[4], C4[4];
    {
        /* A = v19(h3u) */
        float win[22];
#pragma unroll
        for (int k = 0; k < 22; k++) win[k] = h3u[(r0+k)*H3STR + c];
        float a0=0.f,a1=0.f,a2=0.f,a3=0.f;
#pragma unroll
        for (int k = 0; k < 19; k++) { float w=G3W[k];
            a0=fmaf(win[k],w,a0); a1=fmaf(win[k+1],w,a1);
            a2=fmaf(win[k+2],w,a2); a3=fmaf(win[k+3],w,a3); }
        A4[0]=a0; A4[1]=a1; A4[2]=a2; A4[3]=a3;
    }
    {
        /* B,C seeds: -v19(h3i), -v19(h3p) from interleaved window */
        float2 win2[22];
#pragma unroll
        for (int k = 0; k < 22; k++) win2[k] = h3xy[(r0+k)*H3STR + c];
        float b0=0.f,b1=0.f,b2=0.f,b3=0.f;
        float c0=0.f,c1=0.f,c2=0.f,c3=0.f;
#pragma unroll
        for (int k = 0; k < 19; k++) { float w=G3W[k];
            b0=fmaf(win2[k].x,w,b0); b1=fmaf(win2[k+1].x,w,b1);
            b2=fmaf(win2[k+2].x,w,b2); b3=fmaf(win2[k+3].x,w,b3);
            c0=fmaf(win2[k].y,w,c0); c1=fmaf(win2[k+1].y,w,c1);
            c2=fmaf(win2[k+2].y,w,c2); c3=fmaf(win2[k+3].y,w,c3); }
        B4[0]=-b0; B4[1]=-b1; B4[2]=-b2; B4[3]=-b3;
        C4[0]=-c0; C4[1]=-c1; C4[2]=-c2; C4[3]=-c3;
    }
    {
        /* B += v7(h1i), C += v7(h1p) */
        float2 win2[10];
#pragma unroll
        for (int k = 0; k < 10; k++) win2[k] = h1xy[(r0+k)*H3STR + c];
        float b0=0.f,b1=0.f,b2=0.f,b3=0.f;
        float c0=0.f,c1=0.f,c2=0.f,c3=0.f;
#pragma unroll
        for (int k = 0; k < 7; k++) { float w=G1W[k];
            b0=fmaf(win2[k].x,w,b0); b1=fmaf(win2[k+1].x,w,b1);
            b2=fmaf(win2[k+2].x,w,b2); b3=fmaf(win2[k+3].x,w,b3);
            c0=fmaf(win2[k].y,w,c0); c1=fmaf(win2[k+1].y,w,c1);
            c2=fmaf(win2[k+2].y,w,c2); c3=fmaf(win2[k+3].y,w,c3); }
        B4[0]+=b0; B4[1]+=b1; B4[2]+=b2; B4[3]+=b3;
        C4[0]+=c0; C4[1]+=c1; C4[2]+=c2; C4[3]+=c3;
    }

    /* ---- phase 4: pointwise + 3x3 stencils (rolling 3-row float2 window) ---- */
    float a_rc=0.f,a_nb=0.f,a_sxi=0.f,a_syp=0.f,a_ex=0.f,a_ey=0.f;
    float a_ntex=0.f,a_tex=0.f,a_nf=0.f,a_hf=0.f,a_ic=0.f;
    float a_nfb=0.f,a_lf=0.f,a_mid=0.f,a_syn=0.f;

    {
        float2 wA[3], wB[3], wC[3];
        {
            int pp = (r0+8)*RAW_W + (c+11);
            wA[0]=s_xy[pp]; wA[1]=s_xy[pp+1]; wA[2]=s_xy[pp+2];
            pp += RAW_W;
            wB[0]=s_xy[pp]; wB[1]=s_xy[pp+1]; wB[2]=s_xy[pp+2];
            pp += RAW_W;
            wC[0]=s_xy[pp]; wC[1]=s_xy[pp+1]; wC[2]=s_xy[pp+2];
        }
#pragma unroll
        for (int j = 0; j < 4; j++) {
            size_t g = base + (size_t)(gy0 + r0 + j)*IMG_W + (gx0 + c);
            float wv = wmap[g], nv = npred[g], sv = nsyn[g];

            float x00=wA[0].x, x01=wA[1].x, x02=wA[2].x;
            float x10=wB[0].x, x11=wB[1].x, x12=wB[2].x;
            float x20=wC[0].x, x21=wC[1].x, x22=wC[2].x;
            float y00=wA[0].y, y01=wA[1].y, y02=wA[2].y;
            float y10=wB[0].y, y11=wB[1].y, y12=wB[2].y;
            float y20=wC[0].y, y21=wC[1].y, y22=wC[2].y;

            float gxi_ = (x02-x00) + 2.f*(x12-x10) + (x22-x20);
            float gyi_ = (x20-x00) + 2.f*(x21-x01) + (x22-x02);
            float lapi = x01 + x21 + x10 + x12 - 4.f*x11;
            float gxp_ = (y02-y00) + 2.f*(y12-y10) + (y22-y20);
            float gyp_ = (y20-y00) + 2.f*(y21-y01) + (y22-y02);
            float lapp = y01 + y21 + y10 + y12 - 4.f*y11;
            float xv = x11, pv = y11;

            a_rc += fabsf(pv*wv - xv*wv);
            float gmi = sqrtf(fmaf(gxi_,gxi_, fmaf(gyi_,gyi_, 1e-8f)));
            float gmp = sqrtf(fmaf(gxp_,gxp_, fmaf(gyp_,gyp_, 1e-8f)));
            a_ex += fabsf(gxp_-gxi_);
            a_ey += fabsf(gyp_-gyi_);
            bool body = (xv > 0.15f) && (xv < 0.85f);
            bool flat = gmi < 0.03f;
            bool tex  = (gmi > 0.03f) && (gmi < 0.5f);
            if (body) {
                a_nb += 1.f; a_sxi += xv; a_syp += pv;
                int bp = (int)(pv * (float)BINS); bp = bp < 0 ? 0 : (bp > BINS-1 ? BINS-1 : bp);
                int bx = (int)(xv * (float)BINS); bx = bx < 0 ? 0 : (bx > BINS-1 ? BINS-1 : bx);
                atomicAdd(&g_hist[bp], 1u);
                atomicAdd(&g_hist[BINS + bx], 1u);
            }
            if (tex) { a_ntex += 1.f; a_tex += fabsf(gmp - gmi); }
            if (flat) {
                a_nf += 1.f;
                a_hf += fabsf(fabsf(lapp) - 0.3f*fabsf(lapi));
                a_ic += fmaxf(gmp - 2.0f*gmi, 0.f);
                if (body) {
                    a_nfb += 1.f;
                    a_lf  += fabsf(A4[j]);
                    a_mid += fabsf(fabsf(C4[j]) - 0.3f*fabsf(B4[j]));
                    a_syn += fabsf(nv - sv);
                }
            }

            if (j < 3) {
                wA[0]=wB[0]; wA[1]=wB[1]; wA[2]=wB[2];
                wB[0]=wC[0]; wB[1]=wC[1]; wB[2]=wC[2];
                int pp = (r0+11+j)*RAW_W + (c+11);
                wC[0]=s_xy[pp]; wC[1]=s_xy[pp+1]; wC[2]=s_xy[pp+2];
            }
        }
    }

    /* block reduction: warp shuffle -> smem double -> global double */
    {
        float vals[NACC] = {a_rc,a_nb,a_sxi,a_syp,a_ex,a_ey,a_ntex,a_tex,
                            a_nf,a_hf,a_ic,a_nfb,a_lf,a_mid,a_syn};
#pragma unroll
        for (int i = 0; i < NACC; i++) {
            float v = vals[i];
#pragma unroll
            for (int off = 16; off; off >>= 1) v += __shfl_down_sync(0xffffffffu, v, off);
            if ((tid & 31) == 0) atomicAdd(&s_red[i], (double)v);
        }
    }
    __syncthreads();
    if (tid < NACC) atomicAdd(&g_acc[tid], s_red[tid]);

    /* ---- last-block finalize ---- */
    __threadfence();
    if (tid == 0) {
        unsigned int prev = atomicAdd(&g_done, 1u);
        s_islast = (prev == NBLOCKS-1) ? 1u : 0u;
    }
    __syncthreads();
    if (!s_islast) return;
    __threadfence();

    {
        __shared__ unsigned int pre_yp[257], pre_xi2[257];
        __shared__ float qv[8];
        __shared__ float s_fr[2];
        const int t = tid;

        unsigned int syp = 0, sxi = 0;
#pragma unroll
        for (int i = 0; i < 16; i++) {
            syp += g_hist[t*16 + i];
            sxi += g_hist[BINS + t*16 + i];
        }
        pre_yp[t] = syp; pre_xi2[t] = sxi;
        if (t < 8) qv[t] = 0.f;
        __syncthreads();
        if (t == 0) {
            unsigned int run = 0;
            for (int i = 0; i < 256; i++) { unsigned int x = pre_yp[i]; pre_yp[i] = run; run += x; }
            pre_yp[256] = run;
            run = 0;
            for (int i = 0; i < 256; i++) { unsigned int x = pre_xi2[i]; pre_xi2[i] = run; run += x; }
            pre_xi2[256] = run;
        }
        __syncthreads();

        long long n = (long long)pre_xi2[256];
        long long ranks[4] = {0,0,0,0};
        float fr25 = 0.f, fr75 = 0.f;
        if (n > 0) {
            float pos25 = 0.25f * (float)(n-1);
            float pos75 = 0.75f * (float)(n-1);
            fr25 = pos25 - floorf(pos25);
            fr75 = pos75 - floorf(pos75);
            ranks[0] = (long long)floorf(pos25);
            ranks[1] = (long long)ceilf(pos25);
            ranks[2] = (long long)floorf(pos75);
            ranks[3] = (long long)ceilf(pos75);
        }
        if (t == 0) { s_fr[0] = fr25; s_fr[1] = fr75; }
        {
            long long cum = (long long)pre_yp[t];
            for (int i = 0; i < 16; i++) {
                unsigned int cnt = g_hist[t*16 + i];
#pragma unroll
                for (int j = 0; j < 4; j++) {
                    if (ranks[j] >= cum && ranks[j] < cum + (long long)cnt)
                        qv[j] = ((float)(t*16+i) + ((float)(ranks[j]-cum) + 0.5f)/(float)cnt) * (1.0f/(float)BINS);
                }
                cum += cnt;
            }
        }
        {
            long long cum = (long long)pre_xi2[t];
            for (int i = 0; i < 16; i++) {
                unsigned int cnt = g_hist[BINS + t*16 + i];
#pragma unroll
                for (int j = 0; j < 4; j++) {
                    if (ranks[j] >= cum && ranks[j] < cum + (long long)cnt)
                        qv[4+j] = ((float)(t*16+i) + ((float)(ranks[j]-cum) + 0.5f)/(float)cnt) * (1.0f/(float)BINS);
                }
                cum += cnt;
            }
        }
        __syncthreads();

        if (t == 0) {
            double nb      = g_acc[1];
            double rc      = g_acc[0] / NPIXD;
            double edge    = (g_acc[4] + g_acc[5]) / NPIXD;
            double mean_in = g_acc[2] / fmax(nb, 1.0);
            double mean_pr = g_acc[3] / fmax(nb, 1.0);
            float f25 = s_fr[0], f75 = s_fr[1];
            float q25p = qv[0]*(1.f-f25) + qv[1]*f25;
            float q75p = qv[2]*(1.f-f75) + qv[3]*f75;
            float q25i = qv[4]*(1.f-f25) + qv[5]*f25;
            float q75i = qv[6]*(1.f-f75) + qv[7]*f75;
            double dm   = mean_pr - mean_in;
            double dq25 = (double)q25p - (double)q25i;
            double dq75 = (double)q75p - (double)q75i;
            double hu   = dm*dm + 0.5*(dq25*dq25 + dq75*dq75);
            double loss_hu  = (nb > 4096.0) ? hu : 0.0;
            double ntex = g_acc[6];
            double loss_tex = (ntex > 100.0) ? g_acc[7]/fmax(ntex,1.0) : 0.0;
            double nf   = g_acc[8];
            double loss_hf  = (nf > 100.0) ? g_acc[9]/fmax(nf,1.0)  : 0.0;
            double loss_ic  = (nf > 100.0) ? g_acc[10]/fmax(nf,1.0) : 0.0;
            double nfb  = g_acc[11];
            double loss_lf  = (nfb > 100.0) ? g_acc[12]/fmax(nfb,1.0) : 0.0;
            double loss_mid = (nfb > 100.0) ? g_acc[13]/fmax(nfb,1.0) : 0.0;
            double loss_syn = (nfb > 100.0) ? g_acc[14]/fmax(nfb,1.0) : 0.0;
            double total = 2.0*rc + 1.5*loss_hu + 1.0*edge + 0.8*loss_tex
                         + 1.5*loss_hf + 0.8*loss_mid + 0.6*loss_lf
                         + 1.0*loss_syn + 0.8*loss_ic;
            out[0] = (float)total;
        }
        __syncthreads();

        /* self-clean for next graph replay */
        for (int i = t; i < 2*BINS; i += 256) g_hist[i] = 0u;
        if (t < NACC) g_acc[t] = 0.0;
        if (t == 0)  g_done = 0u;
    }
}

extern "C" void kernel_launch(void* const* d_in, const int* in_sizes, int n_in,
                              void* d_out, int out_size)
{
    (void)in_sizes; (void)n_in; (void)out_size;
    const float* ypred = (const float*)d_in[0];
    const float* npred = (const float*)d_in[1];
    const float* xi    = (const float*)d_in[2];
    /* d_in[3] = x_ip1 unused by the reference */
    const float* xmid  = (const float*)d_in[4];
    const float* wmap  = (const float*)d_in[5];
    const float* nsyn  = (const float*)d_in[6];

    cudaFuncSetAttribute(k_main, cudaFuncAttributeMaxDynamicSharedMemorySize,
                         SMEM_FLOATS * (int)sizeof(float));
    dim3 grid(GRID_X, GRID_Y, IMG_B);
    k_main<<<grid, 256, SMEM_FLOATS * sizeof(float)>>>(
        ypred, npred, xi, xmid, wmap, nsyn, (float*)d_out);
}